// round 4
// baseline (speedup 1.0000x reference)
#include <cuda_runtime.h>

#define N_PROP 65536
#define N_TGT  128
#define KTOP   8
#define NPB    32   // proposals per block in the score kernel

typedef unsigned long long u64;

// Scratch (static __device__ — no allocations allowed)
__device__ float g_scoresT[(size_t)N_TGT * N_PROP];   // [T][N] logit keys
__device__ float g_top_val[N_TGT * KTOP];
__device__ int   g_top_idx[N_TGT * KTOP];

// ---- packed f32x2 helpers (sm_100+ FFMA2 path; per-lane IEEE fp32) --------
__device__ __forceinline__ u64 fma2(u64 a, u64 b, u64 c) {
    u64 d;
    asm("fma.rn.f32x2 %0, %1, %2, %3;" : "=l"(d) : "l"(a), "l"(b), "l"(c));
    return d;
}
__device__ __forceinline__ u64 pack2(float lo, float hi) {
    u64 d; asm("mov.b64 %0, {%1, %2};" : "=l"(d) : "f"(lo), "f"(hi)); return d;
}
__device__ __forceinline__ void unpack2(u64 x, float& lo, float& hi) {
    asm("mov.b64 {%0, %1}, %2;" : "=f"(lo), "=f"(hi) : "l"(x));
}

// ---------------------------------------------------------------------------
// Kernel 1: MLP scoring. blockDim=128 (thread = target t), block covers NPB
// proposals; each iteration computes 2 proposals packed into f32x2 lanes.
// key = logit if logit >= 0 else -1.0 (sigmoid monotone; sentinel reproduces
// the thresholded-zeros tie of the reference exactly).
// ---------------------------------------------------------------------------
__global__ __launch_bounds__(128) void score_kernel(
    const float* __restrict__ th, const float* __restrict__ xy,
    const float* __restrict__ di, const float* __restrict__ po,
    const float* __restrict__ ne, const float* __restrict__ io,
    const float* __restrict__ W1, const float* __restrict__ b1,
    const float* __restrict__ W2, const float* __restrict__ b2,
    const float* __restrict__ W3, const float* __restrict__ b3)
{
    // Duplicated (w,w) pairs so LDS.128 yields two ready f32x2 operands.
    __shared__ __align__(16) u64 sW1p[64 * 8];   // [i][k0..k5, biaspair, pad]
    __shared__ __align__(16) u64 sW2p[64 * 32];  // [i][j] pairs (16 KB)
    __shared__ __align__(16) u64 sB2p[32];
    __shared__ float sW3[32];
    __shared__ float sB3;

    const int tid = threadIdx.x;

    for (int x = tid; x < 64 * 8; x += 128) {
        int i = x >> 3, k = x & 7;
        float v = 0.0f;
        if (k < 6)       v = W1[k * 64 + i];
        else if (k == 6) v = b1[i];
        sW1p[x] = pack2(v, v);
    }
    for (int x = tid; x < 64 * 32; x += 128) {
        float v = W2[x];
        sW2p[x] = pack2(v, v);
    }
    if (tid < 32) {
        sW3[tid]  = W3[tid];
        sB2p[tid] = pack2(b2[tid], b2[tid]);
    }
    if (tid == 0) sB3 = b3[0];
    __syncthreads();

    const int t  = tid;            // target index 0..127
    const int n0 = blockIdx.x * NPB;

    for (int nn = 0; nn < NPB; nn += 2) {
        const int na = n0 + nn;
        const int oa = na * N_TGT + t;
        const int ob = oa + N_TGT;

        u64 pf[6];
        {
            float fa0 = 1.0f - fminf(th[oa], 180.0f) * (1.0f / 180.0f);
            float fb0 = 1.0f - fminf(th[ob], 180.0f) * (1.0f / 180.0f);
            float fa1 = 1.0f - fminf(xy[oa], 800.0f) * (1.0f / 800.0f);
            float fb1 = 1.0f - fminf(xy[ob], 800.0f) * (1.0f / 800.0f);
            float fa2 = 1.0f - fminf(di[oa], 800.0f) * (1.0f / 800.0f);
            float fb2 = 1.0f - fminf(di[ob], 800.0f) * (1.0f / 800.0f);
            pf[0] = pack2(fa0, fb0);
            pf[1] = pack2(fa1, fb1);
            pf[2] = pack2(fa2, fb2);
            pf[3] = pack2(po[oa], po[ob]);
            pf[4] = pack2(ne[oa], ne[ob]);
            pf[5] = pack2(io[oa], io[ob]);
        }

        u64 h2[32];
        #pragma unroll
        for (int j = 0; j < 32; j++) h2[j] = sB2p[j];

        #pragma unroll 4
        for (int i = 0; i < 64; i++) {
            const ulonglong2 q0 = ((const ulonglong2*)sW1p)[i * 4 + 0]; // k0,k1
            const ulonglong2 q1 = ((const ulonglong2*)sW1p)[i * 4 + 1]; // k2,k3
            const ulonglong2 q2 = ((const ulonglong2*)sW1p)[i * 4 + 2]; // k4,k5
            u64 h = sW1p[i * 8 + 6];                                    // bias pair

            h = fma2(pf[0], q0.x, h);
            h = fma2(pf[1], q0.y, h);
            h = fma2(pf[2], q1.x, h);
            h = fma2(pf[3], q1.y, h);
            h = fma2(pf[4], q2.x, h);
            h = fma2(pf[5], q2.y, h);

            float hlo, hhi;
            unpack2(h, hlo, hhi);
            hlo = fmaxf(hlo, 0.0f);
            hhi = fmaxf(hhi, 0.0f);
            const u64 hp = pack2(hlo, hhi);

            const ulonglong2* w2row = (const ulonglong2*)&sW2p[i * 32];
            #pragma unroll
            for (int j8 = 0; j8 < 16; j8++) {
                const ulonglong2 w = w2row[j8];
                h2[2 * j8 + 0] = fma2(hp, w.x, h2[2 * j8 + 0]);
                h2[2 * j8 + 1] = fma2(hp, w.y, h2[2 * j8 + 1]);
            }
        }

        // Layer 3: relu then dot (scalar; small)
        float acca = sB3, accb = sB3;
        #pragma unroll
        for (int j = 0; j < 32; j++) {
            float a, b;
            unpack2(h2[j], a, b);
            const float w = sW3[j];
            acca = fmaf(fmaxf(a, 0.0f), w, acca);
            accb = fmaf(fmaxf(b, 0.0f), w, accb);
        }

        float2 keys;
        keys.x = (acca >= 0.0f) ? acca : -1.0f;
        keys.y = (accb >= 0.0f) ? accb : -1.0f;
        *(float2*)&g_scoresT[(size_t)t * N_PROP + na] = keys;
    }
}

// ---------------------------------------------------------------------------
// Kernel 2: per-target top-8, ties broken by lowest index (lax.top_k rule).
// float4 loads; ascending-n scan with strict > keeps earliest index on ties.
// ---------------------------------------------------------------------------
__global__ __launch_bounds__(256) void topk_kernel()
{
    __shared__ float sval[256 * KTOP];
    __shared__ int   sidx[256 * KTOP];

    const int t   = blockIdx.x;
    const int tid = threadIdx.x;
    const float4* __restrict__ col4 = (const float4*)(g_scoresT + (size_t)t * N_PROP);

    float val[KTOP];
    int   idx[KTOP];
    #pragma unroll
    for (int k = 0; k < KTOP; k++) { val[k] = -3.4e38f; idx[k] = 0x7fffffff; }

    for (int q = tid; q < N_PROP / 4; q += 256) {
        const float4 v4 = col4[q];
        const int nb = q * 4;
        float vv[4] = {v4.x, v4.y, v4.z, v4.w};
        #pragma unroll
        for (int u = 0; u < 4; u++) {
            const float v = vv[u];
            if (v > val[KTOP - 1]) {
                val[KTOP - 1] = v; idx[KTOP - 1] = nb + u;
                #pragma unroll
                for (int p = KTOP - 1; p > 0; p--) {
                    if (val[p] > val[p - 1]) {
                        float tv = val[p]; val[p] = val[p - 1]; val[p - 1] = tv;
                        int   ti = idx[p]; idx[p] = idx[p - 1]; idx[p - 1] = ti;
                    }
                }
            }
        }
    }

    #pragma unroll
    for (int k = 0; k < KTOP; k++) { sval[tid * KTOP + k] = val[k]; sidx[tid * KTOP + k] = idx[k]; }
    __syncthreads();

    for (int s = 128; s > 0; s >>= 1) {
        float mv[KTOP]; int mi[KTOP];
        if (tid < s) {
            const float* av = &sval[tid * KTOP];
            const int*   ai = &sidx[tid * KTOP];
            const float* bv = &sval[(tid + s) * KTOP];
            const int*   bi = &sidx[(tid + s) * KTOP];
            int i = 0, j = 0;
            #pragma unroll
            for (int k = 0; k < KTOP; k++) {
                const float va = av[i], vb = bv[j];
                const int   ia = ai[i], ib = bi[j];
                const bool take_a = (va > vb) || (va == vb && ia < ib);
                if (take_a) { mv[k] = va; mi[k] = ia; i++; }
                else        { mv[k] = vb; mi[k] = ib; j++; }
            }
            #pragma unroll
            for (int k = 0; k < KTOP; k++) { sval[tid * KTOP + k] = mv[k]; sidx[tid * KTOP + k] = mi[k]; }
        }
        __syncthreads();
    }

    if (tid == 0) {
        #pragma unroll
        for (int k = 0; k < KTOP; k++) {
            g_top_val[t * KTOP + k] = sval[k];
            g_top_idx[t * KTOP + k] = sidx[k];
        }
    }
}

// ---------------------------------------------------------------------------
// Kernel 3: stable descending rank of targets[:,1], scatter output as float32.
// out = [rows(1024) | cols(1024) | valid(1024)].
// ---------------------------------------------------------------------------
__global__ __launch_bounds__(N_TGT) void assemble_kernel(
    const float* __restrict__ targets, float* __restrict__ out)
{
    __shared__ float key[N_TGT];
    const int t = threadIdx.x;
    key[t] = targets[t * 4 + 1];
    __syncthreads();

    const float kt = key[t];
    int r = 0;
    #pragma unroll 8
    for (int j = 0; j < N_TGT; j++) {
        const float kj = key[j];
        r += (kj > kt) || (kj == kt && j < t);   // stable descending
    }

    #pragma unroll
    for (int k = 0; k < KTOP; k++) {
        const int src = t * KTOP + k;
        const int dst = r * KTOP + k;
        out[dst]        = (float)g_top_idx[src];                  // rows
        out[1024 + dst] = (float)t;                               // cols
        out[2048 + dst] = (g_top_val[src] >= 0.0f) ? 1.0f : 0.0f; // valid
    }
}

// ---------------------------------------------------------------------------
extern "C" void kernel_launch(void* const* d_in, const int* in_sizes, int n_in,
                              void* d_out, int out_size)
{
    const float *th, *xy, *di, *po, *ne, *io, *tg, *W1, *b1, *W2, *b2, *W3, *b3;

    if (n_in >= 13 && in_sizes[0] == 6 * 64) {
        // Alphabetical metadata order
        W1 = (const float*)d_in[0];  W2 = (const float*)d_in[1];
        W3 = (const float*)d_in[2];  b1 = (const float*)d_in[3];
        b2 = (const float*)d_in[4];  b3 = (const float*)d_in[5];
        di = (const float*)d_in[6];  io = (const float*)d_in[7];
        ne = (const float*)d_in[8];  po = (const float*)d_in[9];
        xy = (const float*)d_in[10]; tg = (const float*)d_in[11];
        th = (const float*)d_in[12];
    } else {
        // Insertion (dict) order
        th = (const float*)d_in[0];  xy = (const float*)d_in[1];
        di = (const float*)d_in[2];  po = (const float*)d_in[3];
        ne = (const float*)d_in[4];  io = (const float*)d_in[5];
        tg = (const float*)d_in[6];  W1 = (const float*)d_in[7];
        b1 = (const float*)d_in[8];  W2 = (const float*)d_in[9];
        b2 = (const float*)d_in[10]; W3 = (const float*)d_in[11];
        b3 = (const float*)d_in[12];
    }

    score_kernel<<<N_PROP / NPB, 128>>>(th, xy, di, po, ne, io,
                                        W1, b1, W2, b2, W3, b3);
    topk_kernel<<<N_TGT, 256>>>();
    assemble_kernel<<<1, N_TGT>>>(tg, (float*)d_out);
}

// round 5
// speedup vs baseline: 1.2331x; 1.2331x over previous
#include <cuda_runtime.h>

#define N_PROP 65536
#define N_TGT  128
#define KTOP   8
#define NPB    32   // proposals per block in the score kernel

typedef unsigned long long u64;

// Scratch (static __device__ — no allocations allowed)
__device__ float g_scoresT[(size_t)N_TGT * N_PROP];   // [T][N] logit keys
__device__ float g_top_val[N_TGT * KTOP];
__device__ int   g_top_idx[N_TGT * KTOP];

// ---- packed f32x2 helpers (sm_100+ FFMA2 path; per-lane IEEE fp32) --------
__device__ __forceinline__ u64 fma2(u64 a, u64 b, u64 c) {
    u64 d;
    asm("fma.rn.f32x2 %0, %1, %2, %3;" : "=l"(d) : "l"(a), "l"(b), "l"(c));
    return d;
}
__device__ __forceinline__ u64 pack2(float lo, float hi) {
    u64 d; asm("mov.b64 %0, {%1, %2};" : "=l"(d) : "f"(lo), "f"(hi)); return d;
}
__device__ __forceinline__ void unpack2(u64 x, float& lo, float& hi) {
    asm("mov.b64 {%0, %1}, %2;" : "=f"(lo), "=f"(hi) : "l"(x));
}
__device__ __forceinline__ u64 relu2(u64 x) {
    float lo, hi; unpack2(x, lo, hi);
    return pack2(fmaxf(lo, 0.0f), fmaxf(hi, 0.0f));
}

// ---------------------------------------------------------------------------
// Kernel 1: MLP scoring. blockDim=128 (thread = target t), block covers NPB
// proposals, 2 per iteration.
//  - Layer 1: f32x2 lanes = (proposal a, proposal b); W1 duplicated pairs (4KB).
//  - Layer 2/3: f32x2 lanes = (j, j+1) output pairs; W2/W3 stored as plain
//    consecutive-float bit-packs (NO duplication -> LDS stays at R3 level),
//    hidden activation splatted (h,h) from registers.
// key = logit if logit >= 0 else -1.0 (sigmoid monotone; sentinel reproduces
// the thresholded-zeros tie of the reference exactly).
// ---------------------------------------------------------------------------
__global__ __launch_bounds__(128) void score_kernel(
    const float* __restrict__ th, const float* __restrict__ xy,
    const float* __restrict__ di, const float* __restrict__ po,
    const float* __restrict__ ne, const float* __restrict__ io,
    const float* __restrict__ W1, const float* __restrict__ b1,
    const float* __restrict__ W2, const float* __restrict__ b2,
    const float* __restrict__ W3, const float* __restrict__ b3)
{
    __shared__ __align__(16) u64 sW1p[64 * 8];   // dup pairs [i][k0..k5,bias,pad] 4KB
    __shared__ __align__(16) u64 sW2j[64 * 16];  // [i][j8] = (W2[i][2j8],W2[i][2j8+1]) 8KB
    __shared__ __align__(16) u64 sW3j[16];       // (W3[2j],W3[2j+1])
    __shared__ __align__(16) u64 sB2j[16];       // (b2[2j],b2[2j+1])
    __shared__ float sB3;

    const int tid = threadIdx.x;

    for (int x = tid; x < 64 * 8; x += 128) {
        int i = x >> 3, k = x & 7;
        float v = 0.0f;
        if (k < 6)       v = W1[k * 64 + i];
        else if (k == 6) v = b1[i];
        sW1p[x] = pack2(v, v);
    }
    for (int x = tid; x < 64 * 16; x += 128) {
        sW2j[x] = pack2(W2[2 * x], W2[2 * x + 1]);   // row-major consecutive
    }
    if (tid < 16) {
        sW3j[tid] = pack2(W3[2 * tid], W3[2 * tid + 1]);
        sB2j[tid] = pack2(b2[2 * tid], b2[2 * tid + 1]);
    }
    if (tid == 0) sB3 = b3[0];
    __syncthreads();

    const int t  = tid;            // target index 0..127
    const int n0 = blockIdx.x * NPB;

    for (int nn = 0; nn < NPB; nn += 2) {
        const int na = n0 + nn;
        const int oa = na * N_TGT + t;
        const int ob = oa + N_TGT;

        u64 pf[6];
        {
            float fa0 = 1.0f - fminf(th[oa], 180.0f) * (1.0f / 180.0f);
            float fb0 = 1.0f - fminf(th[ob], 180.0f) * (1.0f / 180.0f);
            float fa1 = 1.0f - fminf(xy[oa], 800.0f) * (1.0f / 800.0f);
            float fb1 = 1.0f - fminf(xy[ob], 800.0f) * (1.0f / 800.0f);
            float fa2 = 1.0f - fminf(di[oa], 800.0f) * (1.0f / 800.0f);
            float fb2 = 1.0f - fminf(di[ob], 800.0f) * (1.0f / 800.0f);
            pf[0] = pack2(fa0, fb0);
            pf[1] = pack2(fa1, fb1);
            pf[2] = pack2(fa2, fb2);
            pf[3] = pack2(po[oa], po[ob]);
            pf[4] = pack2(ne[oa], ne[ob]);
            pf[5] = pack2(io[oa], io[ob]);
        }

        u64 h2a[16], h2b[16];
        #pragma unroll
        for (int j = 0; j < 16; j++) { h2a[j] = sB2j[j]; h2b[j] = sB2j[j]; }

        #pragma unroll 2
        for (int i = 0; i < 64; i++) {
            // Layer 1: proposal-packed (needs duplicated W1 pairs)
            const ulonglong2 q0 = ((const ulonglong2*)sW1p)[i * 4 + 0]; // k0,k1
            const ulonglong2 q1 = ((const ulonglong2*)sW1p)[i * 4 + 1]; // k2,k3
            const ulonglong2 q2 = ((const ulonglong2*)sW1p)[i * 4 + 2]; // k4,k5
            u64 h = sW1p[i * 8 + 6];                                    // bias pair

            h = fma2(pf[0], q0.x, h);
            h = fma2(pf[1], q0.y, h);
            h = fma2(pf[2], q1.x, h);
            h = fma2(pf[3], q1.y, h);
            h = fma2(pf[4], q2.x, h);
            h = fma2(pf[5], q2.y, h);

            float hlo, hhi;
            unpack2(h, hlo, hhi);
            const u64 hap = pack2(fmaxf(hlo, 0.0f), fmaxf(hlo, 0.0f)); // (ha,ha)
            const u64 hbp = pack2(fmaxf(hhi, 0.0f), fmaxf(hhi, 0.0f)); // (hb,hb)

            // Layer 2: j-packed; one W2 row read feeds both proposals
            const ulonglong2* w2row = (const ulonglong2*)&sW2j[i * 16];
            #pragma unroll
            for (int q = 0; q < 8; q++) {
                const ulonglong2 w = w2row[q];
                h2a[2 * q + 0] = fma2(hap, w.x, h2a[2 * q + 0]);
                h2a[2 * q + 1] = fma2(hap, w.y, h2a[2 * q + 1]);
                h2b[2 * q + 0] = fma2(hbp, w.x, h2b[2 * q + 0]);
                h2b[2 * q + 1] = fma2(hbp, w.y, h2b[2 * q + 1]);
            }
        }

        // Layer 3: j-packed relu+dot, then horizontal add
        u64 acpa = 0, acpb = 0;   // bit pattern (0.0f,0.0f)
        #pragma unroll
        for (int j = 0; j < 16; j++) {
            const u64 w = sW3j[j];
            acpa = fma2(relu2(h2a[j]), w, acpa);
            acpb = fma2(relu2(h2b[j]), w, acpb);
        }
        float a0, a1, b0v, b1v;
        unpack2(acpa, a0, a1);
        unpack2(acpb, b0v, b1v);
        const float acca = sB3 + a0 + a1;
        const float accb = sB3 + b0v + b1v;

        float2 keys;
        keys.x = (acca >= 0.0f) ? acca : -1.0f;
        keys.y = (accb >= 0.0f) ? accb : -1.0f;
        *(float2*)&g_scoresT[(size_t)t * N_PROP + na] = keys;
    }
}

// ---------------------------------------------------------------------------
// Kernel 2: per-target top-8, ties broken by lowest index (lax.top_k rule).
// 512 threads/block; float4 loads; strict > keeps earliest index on ties.
// ---------------------------------------------------------------------------
__global__ __launch_bounds__(512) void topk_kernel()
{
    __shared__ float sval[512 * KTOP];
    __shared__ int   sidx[512 * KTOP];

    const int t   = blockIdx.x;
    const int tid = threadIdx.x;
    const float4* __restrict__ col4 = (const float4*)(g_scoresT + (size_t)t * N_PROP);

    float val[KTOP];
    int   idx[KTOP];
    #pragma unroll
    for (int k = 0; k < KTOP; k++) { val[k] = -3.4e38f; idx[k] = 0x7fffffff; }

    for (int q = tid; q < N_PROP / 4; q += 512) {
        const float4 v4 = col4[q];
        const int nb = q * 4;
        float vv[4] = {v4.x, v4.y, v4.z, v4.w};
        #pragma unroll
        for (int u = 0; u < 4; u++) {
            const float v = vv[u];
            if (v > val[KTOP - 1]) {
                val[KTOP - 1] = v; idx[KTOP - 1] = nb + u;
                #pragma unroll
                for (int p = KTOP - 1; p > 0; p--) {
                    if (val[p] > val[p - 1]) {
                        float tv = val[p]; val[p] = val[p - 1]; val[p - 1] = tv;
                        int   ti = idx[p]; idx[p] = idx[p - 1]; idx[p - 1] = ti;
                    }
                }
            }
        }
    }

    #pragma unroll
    for (int k = 0; k < KTOP; k++) { sval[tid * KTOP + k] = val[k]; sidx[tid * KTOP + k] = idx[k]; }
    __syncthreads();

    for (int s = 256; s > 0; s >>= 1) {
        float mv[KTOP]; int mi[KTOP];
        if (tid < s) {
            const float* av = &sval[tid * KTOP];
            const int*   ai = &sidx[tid * KTOP];
            const float* bv = &sval[(tid + s) * KTOP];
            const int*   bi = &sidx[(tid + s) * KTOP];
            int i = 0, j = 0;
            #pragma unroll
            for (int k = 0; k < KTOP; k++) {
                const float va = av[i], vb = bv[j];
                const int   ia = ai[i], ib = bi[j];
                const bool take_a = (va > vb) || (va == vb && ia < ib);
                if (take_a) { mv[k] = va; mi[k] = ia; i++; }
                else        { mv[k] = vb; mi[k] = ib; j++; }
            }
            #pragma unroll
            for (int k = 0; k < KTOP; k++) { sval[tid * KTOP + k] = mv[k]; sidx[tid * KTOP + k] = mi[k]; }
        }
        __syncthreads();
    }

    if (tid == 0) {
        #pragma unroll
        for (int k = 0; k < KTOP; k++) {
            g_top_val[t * KTOP + k] = sval[k];
            g_top_idx[t * KTOP + k] = sidx[k];
        }
    }
}

// ---------------------------------------------------------------------------
// Kernel 3: stable descending rank of targets[:,1], scatter output as float32.
// out = [rows(1024) | cols(1024) | valid(1024)].
// ---------------------------------------------------------------------------
__global__ __launch_bounds__(N_TGT) void assemble_kernel(
    const float* __restrict__ targets, float* __restrict__ out)
{
    __shared__ float key[N_TGT];
    const int t = threadIdx.x;
    key[t] = targets[t * 4 + 1];
    __syncthreads();

    const float kt = key[t];
    int r = 0;
    #pragma unroll 8
    for (int j = 0; j < N_TGT; j++) {
        const float kj = key[j];
        r += (kj > kt) || (kj == kt && j < t);   // stable descending
    }

    #pragma unroll
    for (int k = 0; k < KTOP; k++) {
        const int src = t * KTOP + k;
        const int dst = r * KTOP + k;
        out[dst]        = (float)g_top_idx[src];                  // rows
        out[1024 + dst] = (float)t;                               // cols
        out[2048 + dst] = (g_top_val[src] >= 0.0f) ? 1.0f : 0.0f; // valid
    }
}

// ---------------------------------------------------------------------------
extern "C" void kernel_launch(void* const* d_in, const int* in_sizes, int n_in,
                              void* d_out, int out_size)
{
    const float *th, *xy, *di, *po, *ne, *io, *tg, *W1, *b1, *W2, *b2, *W3, *b3;

    if (n_in >= 13 && in_sizes[0] == 6 * 64) {
        // Alphabetical metadata order
        W1 = (const float*)d_in[0];  W2 = (const float*)d_in[1];
        W3 = (const float*)d_in[2];  b1 = (const float*)d_in[3];
        b2 = (const float*)d_in[4];  b3 = (const float*)d_in[5];
        di = (const float*)d_in[6];  io = (const float*)d_in[7];
        ne = (const float*)d_in[8];  po = (const float*)d_in[9];
        xy = (const float*)d_in[10]; tg = (const float*)d_in[11];
        th = (const float*)d_in[12];
    } else {
        // Insertion (dict) order
        th = (const float*)d_in[0];  xy = (const float*)d_in[1];
        di = (const float*)d_in[2];  po = (const float*)d_in[3];
        ne = (const float*)d_in[4];  io = (const float*)d_in[5];
        tg = (const float*)d_in[6];  W1 = (const float*)d_in[7];
        b1 = (const float*)d_in[8];  W2 = (const float*)d_in[9];
        b2 = (const float*)d_in[10]; W3 = (const float*)d_in[11];
        b3 = (const float*)d_in[12];
    }

    score_kernel<<<N_PROP / NPB, 128>>>(th, xy, di, po, ne, io,
                                        W1, b1, W2, b2, W3, b3);
    topk_kernel<<<N_TGT, 512>>>();
    assemble_kernel<<<1, N_TGT>>>(tg, (float*)d_out);
}